// round 1
// baseline (speedup 1.0000x reference)
#include <cuda_runtime.h>
#include <cstdint>
#include <math.h>

#define BATCH   16
#define NCLS    64
#define CDF     128
#define EDIM    1024

#define MT      128   // rows per CTA (= CDF = one batch's tokens for one class)
#define NT      128   // N tile
#define KT      32    // K tile
#define NTHREADS 256

// row stride (in 32-bit words) for interleaved SMEM tiles; 36 = 32 + 4 pad,
// multiple of 4 so uint4 loads stay 16B-aligned.
#define SROW 36

__device__ __forceinline__ uint32_t f2tf32(float f) {
    uint32_t u;
    asm("cvt.rna.tf32.f32 %0, %1;" : "=r"(u) : "f"(f));
    return u;
}

__device__ __forceinline__ float gelu_erf(float v) {
    return 0.5f * v * (1.0f + erff(v * 0.7071067811865476f));
}

__device__ __forceinline__ void mma_tf32(float4& d,
                                         uint32_t a0, uint32_t a1, uint32_t a2, uint32_t a3,
                                         uint32_t b0, uint32_t b1) {
    asm volatile(
        "mma.sync.aligned.m16n8k8.row.col.f32.tf32.tf32.f32 "
        "{%0,%1,%2,%3}, {%4,%5,%6,%7}, {%8,%9}, {%0,%1,%2,%3};\n"
        : "+f"(d.x), "+f"(d.y), "+f"(d.z), "+f"(d.w)
        : "r"(a0), "r"(a1), "r"(a2), "r"(a3), "r"(b0), "r"(b1));
}

__global__ void __launch_bounds__(NTHREADS, 2)
mlp_head_kernel(const float* __restrict__ x,
                const float* __restrict__ W1,
                const float* __restrict__ b1,
                const float* __restrict__ W2,
                const float* __restrict__ b2,
                float* __restrict__ out)
{
    // Interleaved tf32 tiles: element (r, k) lives at [r*SROW + (k&3)*8 + (k>>2)].
    __shared__ uint32_t As[MT * SROW];   // A tile: 128 rows x 32 k
    __shared__ uint32_t Bs[NT * SROW];   // B tile: 128 n    x 32 k
    __shared__ float sb1[NT];
    __shared__ float sw2[NT];
    __shared__ float s_out[MT];

    const int b    = blockIdx.x;   // batch
    const int c    = blockIdx.y;   // class
    const int tid  = threadIdx.x;
    const int lane = tid & 31;
    const int warp = tid >> 5;
    const int wm   = warp >> 1;    // 0..3 : 32-row slice
    const int wn   = warp & 1;     // 0..1 : 64-col slice

    const float* Abase = x  + ((size_t)b * (NCLS * CDF) + (size_t)c * CDF) * EDIM;
    const float* W1c   = W1 + (size_t)c * EDIM * EDIM;

    if (tid < MT) s_out[tid] = 0.0f;

    for (int n0 = 0; n0 < EDIM; n0 += NT) {
        // accumulators: warp tile 32x64, per-thread 2(m-sub) x 8(n-sub) x float4
        float4 acc[2][8];
        #pragma unroll
        for (int mi = 0; mi < 2; ++mi)
            #pragma unroll
            for (int ni = 0; ni < 8; ++ni)
                acc[mi][ni] = make_float4(0.f, 0.f, 0.f, 0.f);

        for (int k0 = 0; k0 < EDIM; k0 += KT) {
            __syncthreads();   // prior compute / s_out init done before overwrite

            // ---- stage A tile (x rows, k-contiguous) ----
            {
                const float* Ak = Abase + k0;
                const int kq = tid & 7;        // float4 index along k
                const int r0 = tid >> 3;       // 0..31
                #pragma unroll
                for (int it = 0; it < 4; ++it) {
                    int r = r0 + it * 32;
                    float4 v = *(const float4*)(Ak + (size_t)r * EDIM + kq * 4);
                    uint32_t* dst = &As[r * SROW + kq];   // col = i*8 + kq
                    dst[0]  = f2tf32(v.x);
                    dst[8]  = f2tf32(v.y);
                    dst[16] = f2tf32(v.z);
                    dst[24] = f2tf32(v.w);
                }
            }
            // ---- stage B tile (W1 rows are n-contiguous; coalesced scalar loads) ----
            {
                const int n  = tid & 127;
                const int kh = tid >> 7;       // 0..1
                const float* Bp = W1c + (size_t)k0 * EDIM + n0 + n;
                #pragma unroll
                for (int kk = 0; kk < 4; ++kk) {
                    int kbase = kk * 8 + kh * 4;
                    #pragma unroll
                    for (int i = 0; i < 4; ++i) {
                        float v = Bp[(size_t)(kbase + i) * EDIM];
                        Bs[n * SROW + i * 8 + kk * 2 + kh] = f2tf32(v);
                    }
                }
            }
            if (k0 == 0 && tid < NT) {
                sb1[tid] = b1[(size_t)c * EDIM + n0 + tid];
                sw2[tid] = W2[(size_t)c * EDIM + n0 + tid];
            }
            __syncthreads();

            // ---- compute: 4 k-steps of m16n8k8, processed in 2 halves ----
            #pragma unroll
            for (int h = 0; h < 2; ++h) {
                uint4 aq[4];
                uint4 bq[8];
                #pragma unroll
                for (int rg = 0; rg < 4; ++rg) {
                    int row = wm * 32 + rg * 8 + (lane >> 2);
                    aq[rg] = *(const uint4*)&As[row * SROW + (lane & 3) * 8 + h * 4];
                }
                #pragma unroll
                for (int ni = 0; ni < 8; ++ni) {
                    int n = wn * 64 + ni * 8 + (lane >> 2);
                    bq[ni] = *(const uint4*)&Bs[n * SROW + (lane & 3) * 8 + h * 4];
                }
                #pragma unroll
                for (int sh = 0; sh < 2; ++sh) {   // k-step = 2h + sh
                    #pragma unroll
                    for (int mi = 0; mi < 2; ++mi) {
                        uint32_t a0 = sh ? aq[mi * 2].z     : aq[mi * 2].x;
                        uint32_t a2 = sh ? aq[mi * 2].w     : aq[mi * 2].y;
                        uint32_t a1 = sh ? aq[mi * 2 + 1].z : aq[mi * 2 + 1].x;
                        uint32_t a3 = sh ? aq[mi * 2 + 1].w : aq[mi * 2 + 1].y;
                        #pragma unroll
                        for (int ni = 0; ni < 8; ++ni) {
                            uint32_t bb0 = sh ? bq[ni].z : bq[ni].x;
                            uint32_t bb1 = sh ? bq[ni].w : bq[ni].y;
                            mma_tf32(acc[mi][ni], a0, a1, a2, a3, bb0, bb1);
                        }
                    }
                }
            }
        }

        // ---- fused epilogue: bias + erf-GELU + dot(W2) partial reduction ----
        #pragma unroll
        for (int mi = 0; mi < 2; ++mi) {
            #pragma unroll
            for (int hi = 0; hi < 2; ++hi) {
                int row = wm * 32 + mi * 16 + hi * 8 + (lane >> 2);
                float rs = 0.0f;
                #pragma unroll
                for (int ni = 0; ni < 8; ++ni) {
                    float v0 = hi ? acc[mi][ni].z : acc[mi][ni].x;
                    float v1 = hi ? acc[mi][ni].w : acc[mi][ni].y;
                    int col = wn * 64 + ni * 8 + (lane & 3) * 2;
                    float g0 = gelu_erf(v0 + sb1[col]);
                    float g1 = gelu_erf(v1 + sb1[col + 1]);
                    rs += g0 * sw2[col] + g1 * sw2[col + 1];
                }
                rs += __shfl_xor_sync(0xffffffffu, rs, 1);
                rs += __shfl_xor_sync(0xffffffffu, rs, 2);
                if ((lane & 3) == 0) atomicAdd(&s_out[row], rs);
            }
        }
    }

    __syncthreads();
    if (tid < MT) {
        out[(size_t)b * (NCLS * CDF) + (size_t)c * CDF + tid] = s_out[tid] + b2[c];
    }
}

extern "C" void kernel_launch(void* const* d_in, const int* in_sizes, int n_in,
                              void* d_out, int out_size) {
    const float* x  = (const float*)d_in[0];
    const float* W1 = (const float*)d_in[1];
    const float* b1 = (const float*)d_in[2];
    const float* W2 = (const float*)d_in[3];
    const float* b2 = (const float*)d_in[4];
    float* out = (float*)d_out;

    dim3 grid(BATCH, NCLS);   // 16 x 64 = 1024 CTAs
    mlp_head_kernel<<<grid, NTHREADS>>>(x, W1, b1, W2, b2, out);
}

// round 3
// speedup vs baseline: 1.8602x; 1.8602x over previous
#include <cuda_runtime.h>
#include <cstdint>
#include <math.h>

#define BATCH   16
#define NCLS    64
#define CDF     128
#define EDIM    1024

// ===================== common helpers =====================
__device__ __forceinline__ uint32_t f2tf32(float f) {
    uint32_t u; asm("cvt.rna.tf32.f32 %0, %1;" : "=r"(u) : "f"(f)); return u;
}
__device__ __forceinline__ float gelu_erf(float v) {
    return 0.5f * v * (1.0f + erff(v * 0.7071067811865476f));
}

// Feature gate: tcgen05 only exists in arch-specific (sm_103a/sm_100a) passes.
#if defined(__CUDA_ARCH_FEAT_SM103_ALL) || defined(__CUDA_ARCH_FEAT_SM100_ALL) || defined(__CUDA_ARCH_FEAT_SM101_ALL)
#define TCGEN05_OK 1
#else
#define TCGEN05_OK 0
#endif

// ======================================================================
// Path A: tcgen05 tf32 warp-specialized kernel (sm_103a passes only)
// ======================================================================
#define NCHUNK  256        // N columns per TMEM chunk (4 chunks total)
#define KT      32         // K per SMEM tile (4 tcgen05 K=8 steps)
#define NSTAGE  4
#define THREADS_TC 288     // warps 0-3 epilogue, 4-7 stagers, 8 MMA

#define OFF_TMEM   0
#define OFF_MB     8                    // per stage s: full @ 8+16s, empty @ 8+16s+8
#define OFF_CHK    72                   // chunk_done[2] @ 72+8p
#define OFF_EPI    88                   // epi_done[2]   @ 88+8p
#define OFF_SB1    128                  // float[2][256]
#define OFF_SW2    (128 + 2048)         // float[2][256]
#define OFF_TILE   8192
#define STAGE_BYTES 49152               // A 16KB + B 32KB, 1KB aligned
#define BTILE_OFF   16384
#define SMEM_TOTAL (OFF_TILE + NSTAGE * STAGE_BYTES)   // 204800

// idesc: kind::tf32, D=F32(1)@[4], atype=TF32(2)@[7], btype=TF32(2)@[10],
// N>>3 @[17], M>>4 @[24]
#define IDESC_TF32 ((1u<<4) | (2u<<7) | (2u<<10) | ((NCHUNK/8)<<17) | ((128/16)<<24))

#if TCGEN05_OK
__device__ __forceinline__ uint64_t make_desc(uint32_t addr) {
    return (uint64_t(2) << 61) | (uint64_t(1) << 46) | (uint64_t(64) << 32)
         | (uint64_t(1) << 16) | ((uint64_t)(addr >> 4) & 0x3FFF);
}
__device__ __forceinline__ uint32_t smem_u32(const void* p) {
    uint32_t a;
    asm("{ .reg .u64 t; cvta.to.shared.u64 t, %1; cvt.u32.u64 %0, t; }" : "=r"(a) : "l"(p));
    return a;
}
__device__ __forceinline__ void sts128(uint32_t a, uint32_t x, uint32_t y, uint32_t z, uint32_t w) {
    asm volatile("st.shared.v4.b32 [%0], {%1,%2,%3,%4};" :: "r"(a), "r"(x), "r"(y), "r"(z), "r"(w) : "memory");
}
__device__ __forceinline__ void mbar_init(uint32_t a, uint32_t cnt) {
    asm volatile("mbarrier.init.shared.b64 [%0], %1;" :: "r"(a), "r"(cnt) : "memory");
}
__device__ __forceinline__ void mbar_arrive(uint32_t a) {
    asm volatile("mbarrier.arrive.shared.b64 _, [%0];" :: "r"(a) : "memory");
}
__device__ __forceinline__ void mbar_wait(uint32_t a, uint32_t parity) {
    asm volatile(
        "{\n\t.reg .pred P;\n\t"
        "WL%=:\n\t"
        "mbarrier.try_wait.parity.acquire.cta.shared::cta.b64 P, [%0], %1, 0x989680;\n\t"
        "@P bra.uni WD%=;\n\t"
        "bra.uni WL%=;\n\t"
        "WD%=:\n\t}" :: "r"(a), "r"(parity) : "memory");
}
__device__ __forceinline__ void fence_async_proxy() {
    asm volatile("fence.proxy.async.shared::cta;" ::: "memory");
}
__device__ __forceinline__ void tc_commit(uint32_t mbar) {
    asm volatile("tcgen05.commit.cta_group::1.mbarrier::arrive::one.shared::cluster.b64 [%0];"
                 :: "r"(mbar) : "memory");
}
__device__ __forceinline__ void mma_tf32_ss(uint32_t d, uint64_t ad, uint64_t bd,
                                            uint32_t idesc, uint32_t enable) {
    asm volatile(
        "{\n\t.reg .pred p;\n\t"
        "setp.ne.u32 p, %5, 0;\n\t"
        "tcgen05.mma.cta_group::1.kind::tf32 [%0], %1, %2, %3, {%4,%4,%4,%4}, p;\n\t}"
        :: "r"(d), "l"(ad), "l"(bd), "r"(idesc), "r"(0u), "r"(enable) : "memory");
}
#endif  // TCGEN05_OK

__global__ void __launch_bounds__(THREADS_TC, 1)
mlp_head_tc(const float* __restrict__ x,
            const float* __restrict__ W1,
            const float* __restrict__ b1,
            const float* __restrict__ W2,
            const float* __restrict__ b2,
            float* __restrict__ out)
{
#if TCGEN05_OK
    extern __shared__ char smem[];
    const uint32_t sb = smem_u32(smem);

    const int tid  = threadIdx.x;
    const int warp = tid >> 5;
    const int lane = tid & 31;
    const int b    = blockIdx.x;
    const int c    = blockIdx.y;

    const float* Abase = x  + ((size_t)b * (NCLS * CDF) + (size_t)c * CDF) * EDIM;
    const float* W1c   = W1 + (size_t)c * EDIM * EDIM;

    float* sb1s = (float*)(smem + OFF_SB1);
    float* sw2s = (float*)(smem + OFF_SW2);

    if (warp == 8) {
        asm volatile("tcgen05.alloc.cta_group::1.sync.aligned.shared::cta.b32 [%0], %1;"
                     :: "r"(sb + OFF_TMEM), "r"(512u) : "memory");
    }
    if (tid == 0) {
        #pragma unroll
        for (int s = 0; s < NSTAGE; ++s) {
            mbar_init(sb + OFF_MB + s * 16,     128);  // full: 128 staging threads
            mbar_init(sb + OFF_MB + s * 16 + 8, 1);    // empty: 1 commit
        }
        mbar_init(sb + OFF_CHK + 0, 1);   mbar_init(sb + OFF_CHK + 8, 1);
        mbar_init(sb + OFF_EPI + 0, 128); mbar_init(sb + OFF_EPI + 8, 128);
    }
    __syncthreads();

    uint32_t tmem;
    asm volatile("ld.shared.b32 %0, [%1];" : "=r"(tmem) : "r"(sb + OFF_TMEM));

    if (warp >= 4 && warp < 8) {
        // ================= STAGING (warps 4-7, 128 threads) =================
        const int local = tid - 128;
        const int q  = local & 7;    // 16B quad within 128B row (A)
        const int r8 = local >> 3;   // 0..15

        for (int g = 0; g < 4 * (EDIM / KT); ++g) {
            const int s  = g & (NSTAGE - 1);
            const int r  = g >> 2;               // ring round
            const int ci = g >> 5;               // chunk
            const int kt = g & 31;
            const int k0 = kt * KT;
            const int nb = ci * NCHUNK;

            mbar_wait(sb + OFF_MB + s * 16 + 8, (r & 1) ^ 1);   // empty

            const uint32_t a_sm = sb + OFF_TILE + s * STAGE_BYTES;
            const uint32_t b_sm = a_sm + BTILE_OFF;

            // ---- A tile: 128 rows x 32 k (tf32-RNA, SW128) ----
            const float* Ak = Abase + k0;
            #pragma unroll
            for (int ps = 0; ps < 8; ++ps) {
                const int row = ps * 16 + r8;
                float4 v = *(const float4*)(Ak + (size_t)row * EDIM + q * 4);
                uint32_t off = row * 128 + q * 16;
                off ^= (off >> 3) & 0x70;
                sts128(a_sm + off, f2tf32(v.x), f2tf32(v.y), f2tf32(v.z), f2tf32(v.w));
            }
            // ---- B tile: 256 n-rows x 32 k (coalesced scalar loads) ----
            #pragma unroll
            for (int rr = 0; rr < 2; ++rr) {
                const int rowb = local + rr * 128;
                const float* Bp = W1c + (size_t)k0 * EDIM + nb + rowb;
                #pragma unroll
                for (int kk = 0; kk < 8; ++kk) {
                    float v0 = Bp[(size_t)(kk * 4 + 0) * EDIM];
                    float v1 = Bp[(size_t)(kk * 4 + 1) * EDIM];
                    float v2 = Bp[(size_t)(kk * 4 + 2) * EDIM];
                    float v3 = Bp[(size_t)(kk * 4 + 3) * EDIM];
                    uint32_t off = rowb * 128 + kk * 16;
                    off ^= (off >> 3) & 0x70;
                    sts128(b_sm + off, f2tf32(v0), f2tf32(v1), f2tf32(v2), f2tf32(v3));
                }
            }
            fence_async_proxy();
            mbar_arrive(sb + OFF_MB + s * 16);   // full
        }
    } else if (warp == 8) {
        // ================= MMA ISSUE (warp 8, lane 0) =================
        if (lane == 0) {
            uint64_t ad[NSTAGE], bd[NSTAGE];
            #pragma unroll
            for (int s = 0; s < NSTAGE; ++s) {
                ad[s] = make_desc(sb + OFF_TILE + s * STAGE_BYTES);
                bd[s] = make_desc(sb + OFF_TILE + s * STAGE_BYTES + BTILE_OFF);
            }
            int g = 0;
            for (int ci = 0; ci < 4; ++ci) {
                const int p = ci & 1;
                if (ci >= 2) {
                    mbar_wait(sb + OFF_EPI + p * 8, 0);   // D region free
                    asm volatile("tcgen05.fence::after_thread_sync;" ::: "memory");
                }
                const uint32_t dt = tmem + p * NCHUNK;
                for (int kt = 0; kt < 32; ++kt, ++g) {
                    const int s = g & (NSTAGE - 1);
                    const int r = g >> 2;
                    mbar_wait(sb + OFF_MB + s * 16, r & 1);   // full
                    #pragma unroll
                    for (int j = 0; j < 4; ++j) {
                        mma_tf32_ss(dt, ad[s] + j * 2, bd[s] + j * 2,
                                    IDESC_TF32, (kt > 0 || j > 0) ? 1u : 0u);
                    }
                    tc_commit(sb + OFF_MB + s * 16 + 8);      // -> empty
                }
                tc_commit(sb + OFF_CHK + p * 8);              // -> chunk_done
            }
        }
    } else {
        // ================= EPILOGUE (warps 0-3, 128 threads) =================
        float accum = 0.0f;
        for (int ci = 0; ci < 4; ++ci) {
            const int p = ci & 1;
            asm volatile("bar.sync 1, 128;" ::: "memory");
            sb1s[p * 256 + 2 * tid]     = b1[(size_t)c * EDIM + ci * NCHUNK + 2 * tid];
            sb1s[p * 256 + 2 * tid + 1] = b1[(size_t)c * EDIM + ci * NCHUNK + 2 * tid + 1];
            sw2s[p * 256 + 2 * tid]     = W2[(size_t)c * EDIM + ci * NCHUNK + 2 * tid];
            sw2s[p * 256 + 2 * tid + 1] = W2[(size_t)c * EDIM + ci * NCHUNK + 2 * tid + 1];
            asm volatile("bar.sync 1, 128;" ::: "memory");

            mbar_wait(sb + OFF_CHK + p * 8, (ci >> 1) & 1);
            asm volatile("tcgen05.fence::after_thread_sync;" ::: "memory");

            #pragma unroll
            for (int blk = 0; blk < NCHUNK / 32; ++blk) {
                uint32_t rg[32];
                asm volatile(
                    "tcgen05.ld.sync.aligned.32x32b.x32.b32 "
                    "{%0,%1,%2,%3,%4,%5,%6,%7,%8,%9,%10,%11,%12,%13,%14,%15,"
                    "%16,%17,%18,%19,%20,%21,%22,%23,%24,%25,%26,%27,%28,%29,%30,%31}, [%32];"
                    : "=r"(rg[0]),"=r"(rg[1]),"=r"(rg[2]),"=r"(rg[3]),"=r"(rg[4]),"=r"(rg[5]),
                      "=r"(rg[6]),"=r"(rg[7]),"=r"(rg[8]),"=r"(rg[9]),"=r"(rg[10]),"=r"(rg[11]),
                      "=r"(rg[12]),"=r"(rg[13]),"=r"(rg[14]),"=r"(rg[15]),"=r"(rg[16]),"=r"(rg[17]),
                      "=r"(rg[18]),"=r"(rg[19]),"=r"(rg[20]),"=r"(rg[21]),"=r"(rg[22]),"=r"(rg[23]),
                      "=r"(rg[24]),"=r"(rg[25]),"=r"(rg[26]),"=r"(rg[27]),"=r"(rg[28]),"=r"(rg[29]),
                      "=r"(rg[30]),"=r"(rg[31])
                    : "r"(tmem + p * NCHUNK + blk * 32));
                asm volatile("tcgen05.wait::ld.sync.aligned;" ::: "memory");
                #pragma unroll
                for (int j = 0; j < 32; ++j) {
                    const int col = p * 256 + blk * 32 + j;
                    float v = __uint_as_float(rg[j]) + sb1s[col];
                    accum += gelu_erf(v) * sw2s[col];
                }
            }
            asm volatile("tcgen05.fence::before_thread_sync;" ::: "memory");
            mbar_arrive(sb + OFF_EPI + p * 8);
        }
        const int row = warp * 32 + lane;
        out[(size_t)b * (NCLS * CDF) + (size_t)c * CDF + row] = accum + b2[c];
    }

    __syncthreads();
    if (warp == 8) {
        asm volatile("tcgen05.relinquish_alloc_permit.cta_group::1.sync.aligned;" ::: "memory");
        asm volatile("tcgen05.dealloc.cta_group::1.sync.aligned.b32 %0, %1;" :: "r"(tmem), "r"(512u));
    }
#else
    (void)x; (void)W1; (void)b1; (void)W2; (void)b2; (void)out;
#endif
}

// ======================================================================
// Path B: fallback mma.sync tf32 kernel (active only on non-'a' passes)
// ======================================================================
#define MT      128
#define NT      128
#define KTF     32
#define THREADS_FB 256
#define SROW    36

#if !TCGEN05_OK
__device__ __forceinline__ void mma_tf32_frag(float4& d,
                                              uint32_t a0, uint32_t a1, uint32_t a2, uint32_t a3,
                                              uint32_t b0, uint32_t b1) {
    asm volatile(
        "mma.sync.aligned.m16n8k8.row.col.f32.tf32.tf32.f32 "
        "{%0,%1,%2,%3}, {%4,%5,%6,%7}, {%8,%9}, {%0,%1,%2,%3};\n"
        : "+f"(d.x), "+f"(d.y), "+f"(d.z), "+f"(d.w)
        : "r"(a0), "r"(a1), "r"(a2), "r"(a3), "r"(b0), "r"(b1));
}
#endif

__global__ void __launch_bounds__(THREADS_FB, 2)
mlp_head_fb(const float* __restrict__ x,
            const float* __restrict__ W1,
            const float* __restrict__ b1,
            const float* __restrict__ W2,
            const float* __restrict__ b2,
            float* __restrict__ out)
{
#if !TCGEN05_OK
    __shared__ uint32_t As[MT * SROW];
    __shared__ uint32_t Bs[NT * SROW];
    __shared__ float sb1[NT];
    __shared__ float sw2[NT];
    __shared__ float s_out[MT];

    const int b    = blockIdx.x;
    const int c    = blockIdx.y;
    const int tid  = threadIdx.x;
    const int lane = tid & 31;
    const int warp = tid >> 5;
    const int wm   = warp >> 1;
    const int wn   = warp & 1;

    const float* Abase = x  + ((size_t)b * (NCLS * CDF) + (size_t)c * CDF) * EDIM;
    const float* W1c   = W1 + (size_t)c * EDIM * EDIM;

    if (tid < MT) s_out[tid] = 0.0f;

    for (int n0 = 0; n0 < EDIM; n0 += NT) {
        float4 acc[2][8];
        #pragma unroll
        for (int mi = 0; mi < 2; ++mi)
            #pragma unroll
            for (int ni = 0; ni < 8; ++ni)
                acc[mi][ni] = make_float4(0.f, 0.f, 0.f, 0.f);

        for (int k0 = 0; k0 < EDIM; k0 += KTF) {
            __syncthreads();
            {
                const float* Ak = Abase + k0;
                const int kq = tid & 7;
                const int r0 = tid >> 3;
                #pragma unroll
                for (int it = 0; it < 4; ++it) {
                    int r = r0 + it * 32;
                    float4 v = *(const float4*)(Ak + (size_t)r * EDIM + kq * 4);
                    uint32_t* dst = &As[r * SROW + kq];
                    dst[0]  = f2tf32(v.x);
                    dst[8]  = f2tf32(v.y);
                    dst[16] = f2tf32(v.z);
                    dst[24] = f2tf32(v.w);
                }
            }
            {
                const int n  = tid & 127;
                const int kh = tid >> 7;
                const float* Bp = W1c + (size_t)k0 * EDIM + n0 + n;
                #pragma unroll
                for (int kk = 0; kk < 4; ++kk) {
                    int kbase = kk * 8 + kh * 4;
                    #pragma unroll
                    for (int i = 0; i < 4; ++i) {
                        float v = Bp[(size_t)(kbase + i) * EDIM];
                        Bs[n * SROW + i * 8 + kk * 2 + kh] = f2tf32(v);
                    }
                }
            }
            if (k0 == 0 && tid < NT) {
                sb1[tid] = b1[(size_t)c * EDIM + n0 + tid];
                sw2[tid] = W2[(size_t)c * EDIM + n0 + tid];
            }
            __syncthreads();

            #pragma unroll
            for (int h = 0; h < 2; ++h) {
                uint4 aq[4];
                uint4 bq[8];
                #pragma unroll
                for (int rg = 0; rg < 4; ++rg) {
                    int row = wm * 32 + rg * 8 + (lane >> 2);
                    aq[rg] = *(const uint4*)&As[row * SROW + (lane & 3) * 8 + h * 4];
                }
                #pragma unroll
                for (int ni = 0; ni < 8; ++ni) {
                    int n = wn * 64 + ni * 8 + (lane >> 2);
                    bq[ni] = *(const uint4*)&Bs[n * SROW + (lane & 3) * 8 + h * 4];
                }
                #pragma unroll
                for (int sh = 0; sh < 2; ++sh) {
                    #pragma unroll
                    for (int mi = 0; mi < 2; ++mi) {
                        uint32_t a0 = sh ? aq[mi * 2].z     : aq[mi * 2].x;
                        uint32_t a2 = sh ? aq[mi * 2].w     : aq[mi * 2].y;
                        uint32_t a1 = sh ? aq[mi * 2 + 1].z : aq[mi * 2 + 1].x;
                        uint32_t a3 = sh ? aq[mi * 2 + 1].w : aq[mi * 2 + 1].y;
                        #pragma unroll
                        for (int ni = 0; ni < 8; ++ni) {
                            uint32_t bb0 = sh ? bq[ni].z : bq[ni].x;
                            uint32_t bb1 = sh ? bq[ni].w : bq[ni].y;
                            mma_tf32_frag(acc[mi][ni], a0, a1, a2, a3, bb0, bb1);
                        }
                    }
                }
            }
        }

        #pragma unroll
        for (int mi = 0; mi < 2; ++mi) {
            #pragma unroll
            for (int hi = 0; hi < 2; ++hi) {
                int row = wm * 32 + mi * 16 + hi * 8 + (lane >> 2);
                float rs = 0.0f;
                #pragma unroll
                for (int ni = 0; ni < 8; ++ni) {
                    float v0 = hi ? acc[mi][ni].z : acc[mi][ni].x;
                    float v1 = hi ? acc[mi][ni].w : acc[mi][ni].y;
                    int col = wn * 64 + ni * 8 + (lane & 3) * 2;
                    float g0 = gelu_erf(v0 + sb1[col]);
                    float g1 = gelu_erf(v1 + sb1[col + 1]);
                    rs += g0 * sw2[col] + g1 * sw2[col + 1];
                }
                rs += __shfl_xor_sync(0xffffffffu, rs, 1);
                rs += __shfl_xor_sync(0xffffffffu, rs, 2);
                if ((lane & 3) == 0) atomicAdd(&s_out[row], rs);
            }
        }
    }

    __syncthreads();
    if (tid < MT) {
        out[(size_t)b * (NCLS * CDF) + (size_t)c * CDF + tid] = s_out[tid] + b2[c];
    }
#else
    (void)x; (void)W1; (void)b1; (void)W2; (void)b2; (void)out;
#endif
}

// ======================================================================
// Host: launch both; exactly one variant has a non-empty body in the
// SASS image the loader picks.
// ======================================================================
extern "C" void kernel_launch(void* const* d_in, const int* in_sizes, int n_in,
                              void* d_out, int out_size) {
    const float* x  = (const float*)d_in[0];
    const float* W1 = (const float*)d_in[1];
    const float* b1 = (const float*)d_in[2];
    const float* W2 = (const float*)d_in[3];
    const float* b2 = (const float*)d_in[4];
    float* out = (float*)d_out;

    static bool attr_set = false;
    if (!attr_set) {
        cudaFuncSetAttribute(mlp_head_tc, cudaFuncAttributeMaxDynamicSharedMemorySize, SMEM_TOTAL);
        attr_set = true;
    }

    dim3 grid(BATCH, NCLS);   // 1024 CTAs
    mlp_head_tc<<<grid, THREADS_TC, SMEM_TOTAL>>>(x, W1, b1, W2, b2, out);
    mlp_head_fb<<<grid, THREADS_FB>>>(x, W1, b1, W2, b2, out);
}